// round 5
// baseline (speedup 1.0000x reference)
#include <cuda_runtime.h>
#include <cuda_bf16.h>
#include <cstdint>

#define BROWS 32768
#define CDIM  1024
#define CHDIM 256

// ---------------- scratch (device globals; no allocations allowed) ----------------
__device__ uint8_t g_t8[(size_t)BROWS * CDIM];    // LN output, fp8 e4m3
__device__ uint8_t g_h8[(size_t)BROWS * CHDIM];   // GLU output, fp8
__device__ uint8_t g_Wdg8[512 * CDIM];            // interleaved [2j]=WdT_j,[2j+1]=WgT_j (K-major fp8)
__device__ float   g_bdg[512];                    // interleaved bd/bg
__device__ uint8_t g_W1T8[CHDIM * CHDIM];         // [n][k] fp8 (dw folded)
__device__ uint8_t g_W2T8[CHDIM * CHDIM];         // (W2·Wv·Wo)^T fp8
__device__ uint8_t g_WuT8[CDIM * CHDIM];          // (Wu + Wu·Wld·Wlu)^T fp8
__device__ float g_P[CHDIM * CHDIM];              // Wv@Wo
__device__ float g_T16[CHDIM * 16];               // Wu@Wld
__device__ float g_s16[16];                       // bu@Wld
__device__ float g_b1eff[CHDIM];
__device__ float g_b2eff[CHDIM];
__device__ float g_bueff[CDIM];

// ---------------- helpers ----------------
__device__ __forceinline__ void cp16cg(uint32_t s, const void* g) {
    asm volatile("cp.async.cg.shared.global [%0], [%1], 16;\n" :: "r"(s), "l"(g));
}
__device__ __forceinline__ void ldsm4(uint32_t* r, uint32_t addr) {
    asm volatile("ldmatrix.sync.aligned.m8n8.x4.shared.b16 {%0,%1,%2,%3}, [%4];"
                 : "=r"(r[0]), "=r"(r[1]), "=r"(r[2]), "=r"(r[3]) : "r"(addr));
}
__device__ __forceinline__ void mma_fp8(float* c, const uint32_t* a, uint32_t b0, uint32_t b1) {
    asm volatile("mma.sync.aligned.m16n8k32.row.col.f32.e4m3.e4m3.f32 "
                 "{%0,%1,%2,%3}, {%4,%5,%6,%7}, {%8,%9}, {%0,%1,%2,%3};\n"
                 : "+f"(c[0]), "+f"(c[1]), "+f"(c[2]), "+f"(c[3])
                 : "r"(a[0]), "r"(a[1]), "r"(a[2]), "r"(a[3]), "r"(b0), "r"(b1));
}
__device__ __forceinline__ uint16_t pk_e4m3_2(float lo, float hi) {
    uint16_t r;
    asm("cvt.rn.satfinite.e4m3x2.f32 %0, %1, %2;" : "=h"(r) : "f"(hi), "f"(lo));
    return r;
}
__device__ __forceinline__ uint32_t pk_e4m3_4(float a, float b, float c, float d) {
    return (uint32_t)pk_e4m3_2(a, b) | ((uint32_t)pk_e4m3_2(c, d) << 16);
}
__device__ __forceinline__ uint8_t pk_e4m3_1(float v) {
    return (uint8_t)pk_e4m3_2(v, 0.f);
}
__device__ __forceinline__ float sigm(float x) { return 1.f / (1.f + expf(-x)); }
__device__ __forceinline__ float gelu_t(float x) {
    return 0.5f * x * (1.f + tanhf(0.7978845608028654f * (x + 0.044715f * x * x * x)));
}

// ---------------- merged prep kernels (side stream, overlapped with LN) ----------------
__global__ void __launch_bounds__(256) prepA1(
    const float* __restrict__ Wv, const float* __restrict__ Wo,
    const float* __restrict__ W1, const float* __restrict__ dww,
    const float* __restrict__ b1, const float* __restrict__ dwb) {
    __shared__ float rowbuf[256];
    const int b = blockIdx.x, j = threadIdx.x;
    if (b < 256) {
        rowbuf[j] = Wv[b * 256 + j];
        __syncthreads();
        float s = 0.f;
        #pragma unroll 8
        for (int k = 0; k < 256; k++) s += rowbuf[k] * Wo[k * 256 + j];
        g_P[b * 256 + j] = s;
    } else if (b < 512) {
        const int i = b - 256;
        g_W1T8[j * 256 + i] = pk_e4m3_1(dww[i] * W1[i * 256 + j]);
    } else {
        float s = b1[j];
        for (int i = 0; i < 256; i++) s += dwb[i] * W1[i * 256 + j];
        g_b1eff[j] = s;
    }
}
__global__ void __launch_bounds__(256) prepA2(
    const float* __restrict__ Wd, const float* __restrict__ Wg,
    const float* __restrict__ bd, const float* __restrict__ bg,
    const float* __restrict__ Wu, const float* __restrict__ Wld,
    const float* __restrict__ bu) {
    __shared__ float buf[256];
    const int b = blockIdx.x, t = threadIdx.x;
    if (b < 512) {
        const int j = b >> 1;
        const float* W = (b & 1) ? Wg : Wd;
        const int k0 = t * 4;
        ((uint32_t*)g_Wdg8)[b * 256 + t] = pk_e4m3_4(
            W[(k0 + 0) * 256 + j], W[(k0 + 1) * 256 + j],
            W[(k0 + 2) * 256 + j], W[(k0 + 3) * 256 + j]);
    } else if (b == 512) {
        for (int idx = t; idx < 512; idx += 256)
            g_bdg[idx] = (idx & 1) ? bg[idx >> 1] : bd[idx >> 1];
    } else if (b < 769) {
        const int i = b - 513;
        const int r = t & 15, kc = t >> 4;
        float s = 0.f;
        for (int k = kc * 64; k < kc * 64 + 64; k++)
            s += Wu[(size_t)i * 1024 + k] * Wld[k * 16 + r];
        buf[t] = s;
        __syncthreads();
        if (t < 16) {
            float acc = 0.f;
            #pragma unroll
            for (int c = 0; c < 16; c++) acc += buf[c * 16 + t];
            g_T16[i * 16 + t] = acc;
        }
    } else {
        if (t < 16) {
            float s = 0.f;
            for (int k = 0; k < 1024; k++) s += bu[k] * Wld[k * 16 + t];
            g_s16[t] = s;
        }
    }
}
__global__ void __launch_bounds__(256) prepB1(
    const float* __restrict__ W2, const float* __restrict__ b2,
    const float* __restrict__ bv, const float* __restrict__ Wo,
    const float* __restrict__ bo) {
    __shared__ float rowbuf[256];
    const int b = blockIdx.x, j = threadIdx.x;
    if (b < 256) {
        rowbuf[j] = W2[b * 256 + j];
        __syncthreads();
        float s = 0.f;
        #pragma unroll 8
        for (int k = 0; k < 256; k++) s += rowbuf[k] * g_P[k * 256 + j];
        g_W2T8[j * 256 + b] = pk_e4m3_1(s);
    } else {
        float s = bo[j];
        for (int k = 0; k < 256; k++) s += b2[k] * g_P[k * 256 + j] + bv[k] * Wo[k * 256 + j];
        g_b2eff[j] = s;
    }
}
__global__ void __launch_bounds__(256) prepB2(
    const float* __restrict__ Wu, const float* __restrict__ Wlu,
    const float* __restrict__ bu) {
    const int n = blockIdx.x, i = threadIdx.x;
    __shared__ float wl[16];
    __shared__ float sb[256];
    if (i < 16) wl[i] = Wlu[i * 1024 + n];
    __syncthreads();
    float s = Wu[(size_t)i * 1024 + n];
    #pragma unroll
    for (int r = 0; r < 16; r++) s += g_T16[i * 16 + r] * wl[r];
    sb[i] = s;
    if (i == 0) {
        float bb = bu[n];
        #pragma unroll
        for (int r = 0; r < 16; r++) bb += g_s16[r] * wl[r];
        g_bueff[n] = bb;
    }
    __syncthreads();
    if (i < 64)
        ((uint32_t*)g_WuT8)[n * 64 + i] =
            pk_e4m3_4(sb[4 * i], sb[4 * i + 1], sb[4 * i + 2], sb[4 * i + 3]);
}

// ---------------- LayerNorm: x[row,1024] -> fp8 g_t8 ----------------
__global__ void __launch_bounds__(256) ln_kernel(const float* __restrict__ x,
                                                 const float* __restrict__ gamma,
                                                 const float* __restrict__ beta) {
    const int row = blockIdx.x;
    const int tid = threadIdx.x;
    const float4 v = ((const float4*)(x + (size_t)row * CDIM))[tid];
    float s  = v.x + v.y + v.z + v.w;
    float s2 = v.x * v.x + v.y * v.y + v.z * v.z + v.w * v.w;
    #pragma unroll
    for (int o = 16; o > 0; o >>= 1) {
        s  += __shfl_xor_sync(0xffffffffu, s, o);
        s2 += __shfl_xor_sync(0xffffffffu, s2, o);
    }
    __shared__ float rs[8], rq[8];
    const int w = tid >> 5, lane = tid & 31;
    if (lane == 0) { rs[w] = s; rq[w] = s2; }
    __syncthreads();
    float mu = 0.f, e2 = 0.f;
    #pragma unroll
    for (int i = 0; i < 8; i++) { mu += rs[i]; e2 += rq[i]; }
    mu *= (1.f / 1024.f);
    const float var = e2 * (1.f / 1024.f) - mu * mu;
    const float rstd = rsqrtf(var + 1e-5f);
    const float4 gm = ((const float4*)gamma)[tid];
    const float4 bt = ((const float4*)beta)[tid];
    ((uint32_t*)(g_t8 + (size_t)row * CDIM))[tid] = pk_e4m3_4(
        (v.x - mu) * rstd * gm.x + bt.x, (v.y - mu) * rstd * gm.y + bt.y,
        (v.z - mu) * rstd * gm.z + bt.z, (v.w - mu) * rstd * gm.w + bt.w);
}

// ---------------- GEMM1 (GLU): 128x128 tile, 3-stage cp.async, fp8 mma ----------------
__global__ void __launch_bounds__(256, 2) gemm1_glu(
    const uint8_t* __restrict__ A,
    const uint8_t* __restrict__ BT,
    const float* __restrict__ bias,
    uint8_t* __restrict__ out8) {
    constexpr int KDIM = 1024, NKT = 8;
    extern __shared__ __align__(1024) char dsm[];
    const uint32_t Ab = (uint32_t)__cvta_generic_to_shared(dsm);
    const uint32_t Bb = Ab + 49152;
    const int tid = threadIdx.x, lane = tid & 31, w = tid >> 5;
    const int wm = w >> 2, wn = w & 3;
    const int mbase = blockIdx.y * 128, nbase = blockIdx.x * 128;

    float acc[4][4][4];
    #pragma unroll
    for (int mi = 0; mi < 4; mi++)
        #pragma unroll
        for (int nj = 0; nj < 4; nj++)
            #pragma unroll
            for (int q = 0; q < 4; q++) acc[mi][nj][q] = 0.f;

    auto fill = [&](int s, int c) {
        const int k0 = c * 128;
        #pragma unroll
        for (int i = 0; i < 4; i++) {
            const int cid = tid + i * 256;
            const int rr = cid >> 3, cc = cid & 7;
            uint32_t off = (uint32_t)(rr * 128 + cc * 16);
            off ^= (off >> 3) & 0x70;
            cp16cg(Ab + s * 16384 + off, A + (size_t)(mbase + rr) * KDIM + k0 + cc * 16);
        }
        #pragma unroll
        for (int i = 0; i < 4; i++) {
            const int cid = tid + i * 256;
            const int rr = cid >> 3, cc = cid & 7;
            uint32_t off = (uint32_t)(rr * 128 + cc * 16);
            off ^= (off >> 3) & 0x70;
            cp16cg(Bb + s * 16384 + off, BT + (size_t)(nbase + rr) * KDIM + k0 + cc * 16);
        }
        asm volatile("cp.async.commit_group;\n" ::: "memory");
    };

    const int a_r  = wm * 64 + ((lane >> 3) & 1) * 8 + (lane & 7);
    const int a_cb = ((lane >> 4) & 1) * 16;
    const int b_r  = wn * 32 + ((lane >> 4) & 1) * 8 + (lane & 7);
    const int b_cb = ((lane >> 3) & 1) * 16;

    fill(0, 0);
    fill(1, 1);
    int fi = 2;
    for (int i = 0; i < NKT; i++) {
        const int s = i % 3;
        if (i < NKT - 1) asm volatile("cp.async.wait_group 1;\n" ::: "memory");
        else             asm volatile("cp.async.wait_group 0;\n" ::: "memory");
        __syncthreads();
        if (fi < NKT) { fill(fi % 3, fi); fi++; }
        const uint32_t As = Ab + s * 16384, Bs = Bb + s * 16384;
        #pragma unroll
        for (int kk = 0; kk < 4; kk++) {
            uint32_t a[4][4], b[2][4];
            #pragma unroll
            for (int mi = 0; mi < 4; mi++) {
                uint32_t off = (uint32_t)((a_r + mi * 16) * 128 + a_cb + kk * 32);
                off ^= (off >> 3) & 0x70;
                ldsm4(a[mi], As + off);
            }
            #pragma unroll
            for (int njp = 0; njp < 2; njp++) {
                uint32_t off = (uint32_t)((b_r + njp * 16) * 128 + b_cb + kk * 32);
                off ^= (off >> 3) & 0x70;
                ldsm4(b[njp], Bs + off);
            }
            #pragma unroll
            for (int mi = 0; mi < 4; mi++)
                #pragma unroll
                for (int nj = 0; nj < 4; nj++)
                    mma_fp8(acc[mi][nj], a[mi], b[nj >> 1][(nj & 1) * 2],
                            b[nj >> 1][(nj & 1) * 2 + 1]);
        }
    }
    #pragma unroll
    for (int mi = 0; mi < 4; mi++) {
        const int r0 = mbase + wm * 64 + mi * 16 + (lane >> 2);
        const int r1 = r0 + 8;
        #pragma unroll
        for (int nj = 0; nj < 4; nj++) {
            const int col = nbase + wn * 32 + nj * 8 + (lane & 3) * 2;
            const float* c = acc[mi][nj];
            const float b0 = bias[col], b1 = bias[col + 1];
            const int j = col >> 1;
            out8[(size_t)r0 * 256 + j] = pk_e4m3_1((c[0] + b0) * sigm(c[1] + b1));
            out8[(size_t)r1 * 256 + j] = pk_e4m3_1((c[2] + b0) * sigm(c[3] + b1));
        }
    }
}

// ---------------- fused GEMM2+3+4: h8 -> out (one pass per 128-row tile) ----------------
// 512 threads (16 warps, warp tile 32x64). smem planes of 128B rows, SW128 swizzle.
// Stages: A: gelu(h@W1+b1) -> smem fp8 ; B: @W2eff+b2 -> smem fp8 ;
// C: 4 chunks of @WuT(+bueff) with 0.5*h+0.5*x fp32 epilogue. WuT chunks stream
// through the W1/W2 smem regions (double-buffered via cp.async groups).
#define SM_HA   0u
#define SM_ACTB 32768u
#define SM_ACTC 65536u
#define SM_WB0  98304u
#define SM_WB1  163840u
#define FUSED_SMEM 229376

__global__ void __launch_bounds__(512, 1) fused_chain(
    const uint8_t* __restrict__ Hin,
    const float* __restrict__ xres,
    float* __restrict__ outf) {
    extern __shared__ __align__(1024) char dsm[];
    const uint32_t S = (uint32_t)__cvta_generic_to_shared(dsm);
    const int tid = threadIdx.x, lane = tid & 31, w = tid >> 5;
    const int wm = w >> 2, wn = w & 3;
    const int mbase = blockIdx.x * 128;

    const int a_r8 = ((lane >> 3) & 1) * 8 + (lane & 7);
    const int a_cb = ((lane >> 4) & 1) * 16;
    const int b_r8 = ((lane >> 4) & 1) * 8 + (lane & 7);
    const int b_cb = ((lane >> 3) & 1) * 16;

    // ---- async loads: g0 = h tile, g1 = W1, g2 = W2 ----
    #pragma unroll
    for (int i = 0; i < 4; i++) {               // 128 rows x 256B -> 2 planes
        const int id = tid + i * 512;
        const int kh = id >> 10, rem = id & 1023, r = rem >> 3, cc = rem & 7;
        uint32_t off = (uint32_t)(r * 128 + cc * 16);
        off ^= (off >> 3) & 0x70;
        cp16cg(S + SM_HA + kh * 16384 + off, Hin + (size_t)(mbase + r) * 256 + kh * 128 + cc * 16);
    }
    asm volatile("cp.async.commit_group;\n" ::: "memory");
    auto loadW = [&](uint32_t dst, const uint8_t* Wsrc) {  // 256 rows x 256B -> 2 planes
        #pragma unroll
        for (int i = 0; i < 8; i++) {
            const int id = tid + i * 512;
            const int kh = id >> 11, rem = id & 2047, n = rem >> 3, cc = rem & 7;
            uint32_t off = (uint32_t)(n * 128 + cc * 16);
            off ^= (off >> 3) & 0x70;
            cp16cg(S + dst + kh * 32768 + off, Wsrc + (size_t)n * 256 + kh * 128 + cc * 16);
        }
        asm volatile("cp.async.commit_group;\n" ::: "memory");
    };
    loadW(SM_WB0, g_W1T8);
    loadW(SM_WB1, g_W2T8);

    float acc[2][8][4];
    auto zero_acc = [&]() {
        #pragma unroll
        for (int mi = 0; mi < 2; mi++)
            #pragma unroll
            for (int nj = 0; nj < 8; nj++)
                #pragma unroll
                for (int q = 0; q < 4; q++) acc[mi][nj][q] = 0.f;
    };
    auto run_stage = [&](uint32_t aoff, uint32_t boff) {    // 128x256 += A(128x256)@B^T(256x256)
        #pragma unroll
        for (int kk = 0; kk < 8; kk++) {
            const uint32_t ap = S + aoff + (kk >> 2) * 16384;
            const uint32_t bp = S + boff + (kk >> 2) * 32768;
            uint32_t a[2][4], b[4][4];
            #pragma unroll
            for (int mi = 0; mi < 2; mi++) {
                uint32_t off = (uint32_t)((wm * 32 + mi * 16 + a_r8) * 128 + a_cb + (kk & 3) * 32);
                off ^= (off >> 3) & 0x70;
                ldsm4(a[mi], ap + off);
            }
            #pragma unroll
            for (int njp = 0; njp < 4; njp++) {
                uint32_t off = (uint32_t)((wn * 64 + njp * 16 + b_r8) * 128 + b_cb + (kk & 3) * 32);
                off ^= (off >> 3) & 0x70;
                ldsm4(b[njp], bp + off);
            }
            #pragma unroll
            for (int mi = 0; mi < 2; mi++)
                #pragma unroll
                for (int nj = 0; nj < 8; nj++)
                    mma_fp8(acc[mi][nj], a[mi], b[nj >> 1][(nj & 1) * 2],
                            b[nj >> 1][(nj & 1) * 2 + 1]);
        }
    };
    auto store_act = [&](uint32_t dst, const float* bias, bool do_gelu) {
        #pragma unroll
        for (int mi = 0; mi < 2; mi++) {
            const int r0 = wm * 32 + mi * 16 + (lane >> 2);
            #pragma unroll
            for (int nj = 0; nj < 8; nj++) {
                const int c = wn * 64 + nj * 8 + (lane & 3) * 2;
                const float b0 = bias[c], b1 = bias[c + 1];
                const float* a = acc[mi][nj];
                float v00 = a[0] + b0, v01 = a[1] + b1, v10 = a[2] + b0, v11 = a[3] + b1;
                if (do_gelu) { v00 = gelu_t(v00); v01 = gelu_t(v01);
                               v10 = gelu_t(v10); v11 = gelu_t(v11); }
                const uint32_t base = dst + (uint32_t)(c >> 7) * 16384 + (uint32_t)(c & 127);
                uint32_t o0 = base + (uint32_t)r0 * 128;
                uint32_t o1 = base + (uint32_t)(r0 + 8) * 128;
                o0 ^= (o0 >> 3) & 0x70;
                o1 ^= (o1 >> 3) & 0x70;
                *(uint16_t*)(dsm + o0) = pk_e4m3_2(v00, v01);
                *(uint16_t*)(dsm + o1) = pk_e4m3_2(v10, v11);
            }
        }
    };

    // ---- stage A: gelu(h @ W1 + b1) ----
    asm volatile("cp.async.wait_group 1;\n" ::: "memory");   // g0,g1 done; g2 in flight
    __syncthreads();
    zero_acc();
    run_stage(SM_HA, SM_WB0);
    store_act(SM_ACTB, g_b1eff, true);
    __syncthreads();                                          // actB visible; hA/W1 free
    loadW(SM_WB0, g_WuT8);                                    // g3 = WuT chunk0

    // ---- stage B: actB @ W2eff + b2 ----
    asm volatile("cp.async.wait_group 1;\n" ::: "memory");   // g2 done; g3 in flight
    __syncthreads();
    zero_acc();
    run_stage(SM_ACTB, SM_WB1);
    store_act(SM_ACTC, g_b2eff, false);
    __syncthreads();                                          // actC visible; W2 free
    loadW(SM_WB1, g_WuT8 + 65536);                            // g4 = WuT chunk1

    // ---- stage C: 4 chunks of actC @ WuT + residual epilogue ----
    #pragma unroll 1
    for (int c = 0; c < 4; c++) {
        if (c < 3) asm volatile("cp.async.wait_group 1;\n" ::: "memory");
        else       asm volatile("cp.async.wait_group 0;\n" ::: "memory");
        __syncthreads();
        zero_acc();
        run_stage(SM_ACTC, (c & 1) ? SM_WB1 : SM_WB0);
        // epilogue
        #pragma unroll
        for (int mi = 0; mi < 2; mi++) {
            const int r0 = mbase + wm * 32 + mi * 16 + (lane >> 2);
            const int r1 = r0 + 8;
            #pragma unroll
            for (int nj = 0; nj < 8; nj++) {
                const int n = c * 256 + wn * 64 + nj * 8 + (lane & 3) * 2;
                const float b0 = g_bueff[n], b1 = g_bueff[n + 1];
                const float* a = acc[mi][nj];
                const float2 x0 = *(const float2*)&xres[(size_t)r0 * 1024 + n];
                const float2 x1 = *(const float2*)&xres[(size_t)r1 * 1024 + n];
                float2 o0 = make_float2(0.5f * (a[0] + b0) + 0.5f * x0.x,
                                        0.5f * (a[1] + b1) + 0.5f * x0.y);
                float2 o1 = make_float2(0.5f * (a[2] + b0) + 0.5f * x1.x,
                                        0.5f * (a[3] + b1) + 0.5f * x1.y);
                *(float2*)&outf[(size_t)r0 * 1024 + n] = o0;
                *(float2*)&outf[(size_t)r1 * 1024 + n] = o1;
            }
        }
        if (c < 2) {
            __syncthreads();                                   // chunk c buffer free
            loadW((c & 1) ? SM_WB1 : SM_WB0, g_WuT8 + (size_t)(c + 2) * 65536);
        }
    }
}

// ---------------- launch ----------------
extern "C" void kernel_launch(void* const* d_in, const int* in_sizes, int n_in,
                              void* d_out, int out_size) {
    (void)in_sizes; (void)n_in; (void)out_size;
    const float* x    = (const float*)d_in[0];
    const float* ln_g = (const float*)d_in[1];
    const float* ln_b = (const float*)d_in[2];
    const float* Wd   = (const float*)d_in[3];
    const float* bd   = (const float*)d_in[4];
    const float* Wg   = (const float*)d_in[5];
    const float* bg   = (const float*)d_in[6];
    const float* dww  = (const float*)d_in[7];
    const float* dwb  = (const float*)d_in[8];
    const float* W1   = (const float*)d_in[9];
    const float* b1   = (const float*)d_in[10];
    const float* W2   = (const float*)d_in[11];
    const float* b2   = (const float*)d_in[12];
    // d_in[13..16] = Wq, bq, Wk, bk : dead (softmax over a single key == 1)
    const float* Wv   = (const float*)d_in[17];
    const float* bv   = (const float*)d_in[18];
    const float* Wo   = (const float*)d_in[19];
    const float* bo   = (const float*)d_in[20];
    const float* Wu   = (const float*)d_in[21];
    const float* bu   = (const float*)d_in[22];
    const float* Wld  = (const float*)d_in[23];
    const float* Wlu  = (const float*)d_in[24];
    float* out = (float*)d_out;

    void *p_t, *p_h, *p_Wdg, *p_bdg, *p_h8;
    cudaGetSymbolAddress(&p_t,   g_t8);
    cudaGetSymbolAddress(&p_h,   g_h8);
    cudaGetSymbolAddress(&p_Wdg, g_Wdg8);
    cudaGetSymbolAddress(&p_bdg, g_bdg);
    p_h8 = p_h;

    static cudaStream_t s2 = nullptr;
    static cudaEvent_t evF = nullptr, evJ = nullptr;
    static bool attr_done = false;
    if (!attr_done) {
        cudaFuncSetAttribute(gemm1_glu, cudaFuncAttributeMaxDynamicSharedMemorySize, 98304);
        cudaFuncSetAttribute(fused_chain, cudaFuncAttributeMaxDynamicSharedMemorySize, FUSED_SMEM);
        cudaStreamCreateWithFlags(&s2, cudaStreamNonBlocking);
        cudaEventCreateWithFlags(&evF, cudaEventDisableTiming);
        cudaEventCreateWithFlags(&evJ, cudaEventDisableTiming);
        attr_done = true;
    }

    // fork: preps on side stream, LN on main stream (independent)
    cudaEventRecord(evF, 0);
    cudaStreamWaitEvent(s2, evF, 0);
    prepA1<<<513, 256, 0, s2>>>(Wv, Wo, W1, dww, b1, dwb);
    prepA2<<<770, 256, 0, s2>>>(Wd, Wg, bd, bg, Wu, Wld, bu);
    prepB1<<<257, 256, 0, s2>>>(W2, b2, bv, Wo, bo);
    prepB2<<<1024, 256, 0, s2>>>(Wu, Wlu, bu);
    cudaEventRecord(evJ, s2);

    ln_kernel<<<BROWS, 256>>>(x, ln_g, ln_b);
    cudaStreamWaitEvent(0, evJ, 0);

    gemm1_glu<<<dim3(4, 256), 256, 98304>>>(
        (const uint8_t*)p_t, (const uint8_t*)p_Wdg, (const float*)p_bdg, (uint8_t*)p_h8);
    fused_chain<<<256, 512, FUSED_SMEM>>>((const uint8_t*)p_h8, x, out);
}

// round 7
// speedup vs baseline: 1.2986x; 1.2986x over previous
#include <cuda_runtime.h>
#include <cuda_bf16.h>
#include <cstdint>

#define BROWS 32768
#define CDIM  1024
#define CHDIM 256

// ---------------- scratch (device globals; no allocations allowed) ----------------
__device__ uint8_t g_t8[(size_t)BROWS * CDIM];    // LN output, fp8 e4m3
__device__ uint8_t g_h8[(size_t)BROWS * CHDIM];   // GLU output, fp8
__device__ uint8_t g_g8[(size_t)BROWS * CHDIM];   // gelu(FFN1), fp8
__device__ uint8_t g_m8[(size_t)BROWS * CHDIM];   // FFN2∘attn output, fp8
__device__ uint8_t g_Wdg8[512 * CDIM];            // interleaved [2j]=WdT_j,[2j+1]=WgT_j (K-major fp8)
__device__ float   g_bdg[512];                    // interleaved bd/bg
__device__ uint8_t g_W1T8[CHDIM * CHDIM];         // [n][k] fp8 (dw folded)
__device__ uint8_t g_W2T8[CHDIM * CHDIM];         // (W2·Wv·Wo)^T fp8
__device__ uint8_t g_WuT8[CDIM * CHDIM];          // (Wu + Wu·Wld·Wlu)^T fp8
__device__ float g_P[CHDIM * CHDIM];              // Wv@Wo
__device__ float g_T16[CHDIM * 16];               // Wu@Wld
__device__ float g_s16[16];                       // bu@Wld
__device__ float g_b1eff[CHDIM];
__device__ float g_b2eff[CHDIM];
__device__ float g_bueff[CDIM];

// ---------------- helpers ----------------
__device__ __forceinline__ void cp16cg(uint32_t s, const void* g) {
    asm volatile("cp.async.cg.shared.global [%0], [%1], 16;\n" :: "r"(s), "l"(g));
}
__device__ __forceinline__ void ldsm4(uint32_t* r, uint32_t addr) {
    asm volatile("ldmatrix.sync.aligned.m8n8.x4.shared.b16 {%0,%1,%2,%3}, [%4];"
                 : "=r"(r[0]), "=r"(r[1]), "=r"(r[2]), "=r"(r[3]) : "r"(addr));
}
__device__ __forceinline__ void mma_fp8(float* c, const uint32_t* a, uint32_t b0, uint32_t b1) {
    asm volatile("mma.sync.aligned.m16n8k32.row.col.f32.e4m3.e4m3.f32 "
                 "{%0,%1,%2,%3}, {%4,%5,%6,%7}, {%8,%9}, {%0,%1,%2,%3};\n"
                 : "+f"(c[0]), "+f"(c[1]), "+f"(c[2]), "+f"(c[3])
                 : "r"(a[0]), "r"(a[1]), "r"(a[2]), "r"(a[3]), "r"(b0), "r"(b1));
}
__device__ __forceinline__ uint16_t pk_e4m3_2(float lo, float hi) {
    uint16_t r;
    asm("cvt.rn.satfinite.e4m3x2.f32 %0, %1, %2;" : "=h"(r) : "f"(hi), "f"(lo));
    return r;
}
__device__ __forceinline__ uint32_t pk_e4m3_4(float a, float b, float c, float d) {
    return (uint32_t)pk_e4m3_2(a, b) | ((uint32_t)pk_e4m3_2(c, d) << 16);
}
__device__ __forceinline__ uint8_t pk_e4m3_1(float v) {
    return (uint8_t)pk_e4m3_2(v, 0.f);
}
__device__ __forceinline__ float sigm(float x) { return 1.f / (1.f + expf(-x)); }
__device__ __forceinline__ float gelu_t(float x) {
    return 0.5f * x * (1.f + tanhf(0.7978845608028654f * (x + 0.044715f * x * x * x)));
}

// ---------------- prep1: all weight transforms with no internal deps ----------------
// blocks: [0,256) P=Wv@Wo | [256,512) W1T8 | 512 b1eff | [513,1025) Wdg8 |
//         1025 bdg | [1026,1282) T16 | 1282 s16
__global__ void __launch_bounds__(256) prep1(
    const float* __restrict__ Wv, const float* __restrict__ Wo,
    const float* __restrict__ W1, const float* __restrict__ dww,
    const float* __restrict__ b1, const float* __restrict__ dwb,
    const float* __restrict__ Wd, const float* __restrict__ Wg,
    const float* __restrict__ bd, const float* __restrict__ bg,
    const float* __restrict__ Wu, const float* __restrict__ Wld,
    const float* __restrict__ bu) {
    __shared__ float buf[256];
    const int b = blockIdx.x, t = threadIdx.x;
    if (b < 256) {
        buf[t] = Wv[b * 256 + t];
        __syncthreads();
        float s = 0.f;
        #pragma unroll 8
        for (int k = 0; k < 256; k++) s += buf[k] * Wo[k * 256 + t];
        g_P[b * 256 + t] = s;
    } else if (b < 512) {
        const int i = b - 256;
        g_W1T8[t * 256 + i] = pk_e4m3_1(dww[i] * W1[i * 256 + t]);
    } else if (b == 512) {
        float s = b1[t];
        for (int i = 0; i < 256; i++) s += dwb[i] * W1[i * 256 + t];
        g_b1eff[t] = s;
    } else if (b < 1025) {
        const int f = b - 513;
        const int j = f >> 1;
        const float* W = (f & 1) ? Wg : Wd;
        const int k0 = t * 4;
        ((uint32_t*)g_Wdg8)[f * 256 + t] = pk_e4m3_4(
            W[(k0 + 0) * 256 + j], W[(k0 + 1) * 256 + j],
            W[(k0 + 2) * 256 + j], W[(k0 + 3) * 256 + j]);
    } else if (b == 1025) {
        for (int idx = t; idx < 512; idx += 256)
            g_bdg[idx] = (idx & 1) ? bg[idx >> 1] : bd[idx >> 1];
    } else if (b < 1282) {
        const int i = b - 1026;
        const int r = t & 15, kc = t >> 4;
        float s = 0.f;
        for (int k = kc * 64; k < kc * 64 + 64; k++)
            s += Wu[(size_t)i * 1024 + k] * Wld[k * 16 + r];
        buf[t] = s;
        __syncthreads();
        if (t < 16) {
            float acc = 0.f;
            #pragma unroll
            for (int c = 0; c < 16; c++) acc += buf[c * 16 + t];
            g_T16[i * 16 + t] = acc;
        }
    } else {
        if (t < 16) {
            float s = 0.f;
            for (int k = 0; k < 1024; k++) s += bu[k] * Wld[k * 16 + t];
            g_s16[t] = s;
        }
    }
}
// ---------------- prep2: transforms depending on P / T16 / s16 ----------------
// blocks: [0,256) W2T8 | 256 b2eff | [257,1281) WuT8 + bueff
__global__ void __launch_bounds__(256) prep2(
    const float* __restrict__ W2, const float* __restrict__ b2,
    const float* __restrict__ bv, const float* __restrict__ Wo,
    const float* __restrict__ bo,
    const float* __restrict__ Wu, const float* __restrict__ Wlu,
    const float* __restrict__ bu) {
    __shared__ float buf[256];
    __shared__ float wl[16];
    const int b = blockIdx.x, t = threadIdx.x;
    if (b < 256) {
        buf[t] = W2[b * 256 + t];
        __syncthreads();
        float s = 0.f;
        #pragma unroll 8
        for (int k = 0; k < 256; k++) s += buf[k] * g_P[k * 256 + t];
        g_W2T8[t * 256 + b] = pk_e4m3_1(s);
    } else if (b == 256) {
        float s = bo[t];
        for (int k = 0; k < 256; k++) s += b2[k] * g_P[k * 256 + t] + bv[k] * Wo[k * 256 + t];
        g_b2eff[t] = s;
    } else {
        const int n = b - 257;
        if (t < 16) wl[t] = Wlu[t * 1024 + n];
        __syncthreads();
        float s = Wu[(size_t)t * 1024 + n];
        #pragma unroll
        for (int r = 0; r < 16; r++) s += g_T16[t * 16 + r] * wl[r];
        buf[t] = s;
        if (t == 0) {
            float bb = bu[n];
            #pragma unroll
            for (int r = 0; r < 16; r++) bb += g_s16[r] * wl[r];
            g_bueff[n] = bb;
        }
        __syncthreads();
        if (t < 64)
            ((uint32_t*)g_WuT8)[n * 64 + t] =
                pk_e4m3_4(buf[4 * t], buf[4 * t + 1], buf[4 * t + 2], buf[4 * t + 3]);
    }
}

// ---------------- LayerNorm: x[row,1024] -> fp8 g_t8 ----------------
__global__ void __launch_bounds__(256) ln_kernel(const float* __restrict__ x,
                                                 const float* __restrict__ gamma,
                                                 const float* __restrict__ beta) {
    const int row = blockIdx.x;
    const int tid = threadIdx.x;
    const float4 v = ((const float4*)(x + (size_t)row * CDIM))[tid];
    float s  = v.x + v.y + v.z + v.w;
    float s2 = v.x * v.x + v.y * v.y + v.z * v.z + v.w * v.w;
    #pragma unroll
    for (int o = 16; o > 0; o >>= 1) {
        s  += __shfl_xor_sync(0xffffffffu, s, o);
        s2 += __shfl_xor_sync(0xffffffffu, s2, o);
    }
    __shared__ float rs[8], rq[8];
    const int w = tid >> 5, lane = tid & 31;
    if (lane == 0) { rs[w] = s; rq[w] = s2; }
    __syncthreads();
    float mu = 0.f, e2 = 0.f;
    #pragma unroll
    for (int i = 0; i < 8; i++) { mu += rs[i]; e2 += rq[i]; }
    mu *= (1.f / 1024.f);
    const float var = e2 * (1.f / 1024.f) - mu * mu;
    const float rstd = rsqrtf(var + 1e-5f);
    const float4 gm = ((const float4*)gamma)[tid];
    const float4 bt = ((const float4*)beta)[tid];
    ((uint32_t*)(g_t8 + (size_t)row * CDIM))[tid] = pk_e4m3_4(
        (v.x - mu) * rstd * gm.x + bt.x, (v.y - mu) * rstd * gm.y + bt.y,
        (v.z - mu) * rstd * gm.z + bt.z, (v.w - mu) * rstd * gm.w + bt.w);
}

// ---------------- FP8 QMMA GEMM: 128x128 CTA tile, KT=128B, 3-stage cp.async ----------
// MODE 0: GLU over interleaved (d,g) adjacent cols -> fp8 [.,256]
// MODE 1: gelu(acc+bias) -> fp8   MODE 2: acc+bias -> fp8
// MODE 3: 0.5*(acc+bias) + 0.5*x -> fp32 [.,1024]
template<int KDIM, int MODE>
__global__ void __launch_bounds__(256, 2) gemm_fp8(
    const uint8_t* __restrict__ A,
    const uint8_t* __restrict__ BT,
    const float* __restrict__ bias,
    const float* __restrict__ xres,
    uint8_t* __restrict__ out8,
    float* __restrict__ outf) {
    constexpr int NKT = KDIM / 128;
    extern __shared__ __align__(1024) char dsm[];
    const uint32_t Ab = (uint32_t)__cvta_generic_to_shared(dsm);  // [3][128][128B]
    const uint32_t Bb = Ab + 49152;                               // [3][128][128B]
    const int tid = threadIdx.x, lane = tid & 31, w = tid >> 5;
    const int wm = w >> 2, wn = w & 3;
    const int mbase = blockIdx.y * 128, nbase = blockIdx.x * 128;

    float acc[4][4][4];
    #pragma unroll
    for (int mi = 0; mi < 4; mi++)
        #pragma unroll
        for (int nj = 0; nj < 4; nj++)
            #pragma unroll
            for (int q = 0; q < 4; q++) acc[mi][nj][q] = 0.f;

    auto fill = [&](int s, int c) {
        const int k0 = c * 128;
        #pragma unroll
        for (int i = 0; i < 4; i++) {
            const int cid = tid + i * 256;
            const int rr = cid >> 3, cc = cid & 7;
            uint32_t off = (uint32_t)(rr * 128 + cc * 16);
            off ^= (off >> 3) & 0x70;
            cp16cg(Ab + s * 16384 + off, A + (size_t)(mbase + rr) * KDIM + k0 + cc * 16);
        }
        #pragma unroll
        for (int i = 0; i < 4; i++) {
            const int cid = tid + i * 256;
            const int rr = cid >> 3, cc = cid & 7;
            uint32_t off = (uint32_t)(rr * 128 + cc * 16);
            off ^= (off >> 3) & 0x70;
            cp16cg(Bb + s * 16384 + off, BT + (size_t)(nbase + rr) * KDIM + k0 + cc * 16);
        }
        asm volatile("cp.async.commit_group;\n" ::: "memory");
    };

    const int a_r  = wm * 64 + ((lane >> 3) & 1) * 8 + (lane & 7);
    const int a_cb = ((lane >> 4) & 1) * 16;
    const int b_r  = wn * 32 + ((lane >> 4) & 1) * 8 + (lane & 7);
    const int b_cb = ((lane >> 3) & 1) * 16;

    fill(0, 0);
    if (NKT > 1) fill(1, 1);
    int fi = 2;
    for (int i = 0; i < NKT; i++) {
        const int s = i % 3;
        if (i < NKT - 1) asm volatile("cp.async.wait_group 1;\n" ::: "memory");
        else             asm volatile("cp.async.wait_group 0;\n" ::: "memory");
        __syncthreads();
        if (fi < NKT) { fill(fi % 3, fi); fi++; }
        const uint32_t As = Ab + s * 16384, Bs = Bb + s * 16384;
        #pragma unroll
        for (int kk = 0; kk < 4; kk++) {
            uint32_t a[4][4], b[2][4];
            #pragma unroll
            for (int mi = 0; mi < 4; mi++) {
                uint32_t off = (uint32_t)((a_r + mi * 16) * 128 + a_cb + kk * 32);
                off ^= (off >> 3) & 0x70;
                ldsm4(a[mi], As + off);
            }
            #pragma unroll
            for (int njp = 0; njp < 2; njp++) {
                uint32_t off = (uint32_t)((b_r + njp * 16) * 128 + b_cb + kk * 32);
                off ^= (off >> 3) & 0x70;
                ldsm4(b[njp], Bs + off);
            }
            #pragma unroll
            for (int mi = 0; mi < 4; mi++)
                #pragma unroll
                for (int nj = 0; nj < 4; nj++)
                    mma_fp8(acc[mi][nj], a[mi], b[nj >> 1][(nj & 1) * 2],
                            b[nj >> 1][(nj & 1) * 2 + 1]);
        }
    }

    #pragma unroll
    for (int mi = 0; mi < 4; mi++) {
        const int r0 = mbase + wm * 64 + mi * 16 + (lane >> 2);
        const int r1 = r0 + 8;
        #pragma unroll
        for (int nj = 0; nj < 4; nj++) {
            const int col = nbase + wn * 32 + nj * 8 + (lane & 3) * 2;
            const float* c = acc[mi][nj];
            if constexpr (MODE == 0) {
                const float b0 = bias[col], b1 = bias[col + 1];
                const int j = col >> 1;
                out8[(size_t)r0 * 256 + j] = pk_e4m3_1((c[0] + b0) * sigm(c[1] + b1));
                out8[(size_t)r1 * 256 + j] = pk_e4m3_1((c[2] + b0) * sigm(c[3] + b1));
            } else if constexpr (MODE == 1 || MODE == 2) {
                const float b0 = bias[col], b1 = bias[col + 1];
                float v00 = c[0] + b0, v01 = c[1] + b1, v10 = c[2] + b0, v11 = c[3] + b1;
                if constexpr (MODE == 1) {
                    v00 = gelu_t(v00); v01 = gelu_t(v01); v10 = gelu_t(v10); v11 = gelu_t(v11);
                }
                *(uint16_t*)&out8[(size_t)r0 * 256 + col] = pk_e4m3_2(v00, v01);
                *(uint16_t*)&out8[(size_t)r1 * 256 + col] = pk_e4m3_2(v10, v11);
            } else {
                const float b0 = bias[col], b1 = bias[col + 1];
                const float2 x0 = *(const float2*)&xres[(size_t)r0 * 1024 + col];
                const float2 x1 = *(const float2*)&xres[(size_t)r1 * 1024 + col];
                float2 o0 = make_float2(0.5f * (c[0] + b0) + 0.5f * x0.x,
                                        0.5f * (c[1] + b1) + 0.5f * x0.y);
                float2 o1 = make_float2(0.5f * (c[2] + b0) + 0.5f * x1.x,
                                        0.5f * (c[3] + b1) + 0.5f * x1.y);
                *(float2*)&outf[(size_t)r0 * 1024 + col] = o0;
                *(float2*)&outf[(size_t)r1 * 1024 + col] = o1;
            }
        }
    }
}

// ---------------- launch ----------------
extern "C" void kernel_launch(void* const* d_in, const int* in_sizes, int n_in,
                              void* d_out, int out_size) {
    (void)in_sizes; (void)n_in; (void)out_size;
    const float* x    = (const float*)d_in[0];
    const float* ln_g = (const float*)d_in[1];
    const float* ln_b = (const float*)d_in[2];
    const float* Wd   = (const float*)d_in[3];
    const float* bd   = (const float*)d_in[4];
    const float* Wg   = (const float*)d_in[5];
    const float* bg   = (const float*)d_in[6];
    const float* dww  = (const float*)d_in[7];
    const float* dwb  = (const float*)d_in[8];
    const float* W1   = (const float*)d_in[9];
    const float* b1   = (const float*)d_in[10];
    const float* W2   = (const float*)d_in[11];
    const float* b2   = (const float*)d_in[12];
    // d_in[13..16] = Wq, bq, Wk, bk : dead (softmax over a single key == 1)
    const float* Wv   = (const float*)d_in[17];
    const float* bv   = (const float*)d_in[18];
    const float* Wo   = (const float*)d_in[19];
    const float* bo   = (const float*)d_in[20];
    const float* Wu   = (const float*)d_in[21];
    const float* bu   = (const float*)d_in[22];
    const float* Wld  = (const float*)d_in[23];
    const float* Wlu  = (const float*)d_in[24];
    float* out = (float*)d_out;

    void *p_t, *p_h, *p_g, *p_m, *p_Wdg, *p_bdg, *p_W1, *p_W2, *p_Wu, *p_b1, *p_b2, *p_bu;
    cudaGetSymbolAddress(&p_t,   g_t8);
    cudaGetSymbolAddress(&p_h,   g_h8);
    cudaGetSymbolAddress(&p_g,   g_g8);
    cudaGetSymbolAddress(&p_m,   g_m8);
    cudaGetSymbolAddress(&p_Wdg, g_Wdg8);
    cudaGetSymbolAddress(&p_bdg, g_bdg);
    cudaGetSymbolAddress(&p_W1,  g_W1T8);
    cudaGetSymbolAddress(&p_W2,  g_W2T8);
    cudaGetSymbolAddress(&p_Wu,  g_WuT8);
    cudaGetSymbolAddress(&p_b1,  g_b1eff);
    cudaGetSymbolAddress(&p_b2,  g_b2eff);
    cudaGetSymbolAddress(&p_bu,  g_bueff);

    constexpr int DSM = 98304;  // 3 stages x (16KB A + 16KB B)
    static bool attr_done = false;
    if (!attr_done) {
        cudaFuncSetAttribute(gemm_fp8<1024, 0>, cudaFuncAttributeMaxDynamicSharedMemorySize, DSM);
        cudaFuncSetAttribute(gemm_fp8<256, 1>,  cudaFuncAttributeMaxDynamicSharedMemorySize, DSM);
        cudaFuncSetAttribute(gemm_fp8<256, 2>,  cudaFuncAttributeMaxDynamicSharedMemorySize, DSM);
        cudaFuncSetAttribute(gemm_fp8<256, 3>,  cudaFuncAttributeMaxDynamicSharedMemorySize, DSM);
        attr_done = true;
    }

    // launch order: prep1(0), prep2(1), ln(2), GEMM1(3) <- ncu -s5 lands here,
    // gemm2(4), gemm3(5), gemm4(6)
    prep1<<<1283, 256>>>(Wv, Wo, W1, dww, b1, dwb, Wd, Wg, bd, bg, Wu, Wld, bu);
    prep2<<<1281, 256>>>(W2, b2, bv, Wo, bo, Wu, Wlu, bu);
    ln_kernel<<<BROWS, 256>>>(x, ln_g, ln_b);

    gemm_fp8<1024, 0><<<dim3(4, 256), 256, DSM>>>(
        (const uint8_t*)p_t, (const uint8_t*)p_Wdg,
        (const float*)p_bdg, nullptr, (uint8_t*)p_h, nullptr);
    gemm_fp8<256, 1><<<dim3(2, 256), 256, DSM>>>(
        (const uint8_t*)p_h, (const uint8_t*)p_W1,
        (const float*)p_b1, nullptr, (uint8_t*)p_g, nullptr);
    gemm_fp8<256, 2><<<dim3(2, 256), 256, DSM>>>(
        (const uint8_t*)p_g, (const uint8_t*)p_W2,
        (const float*)p_b2, nullptr, (uint8_t*)p_m, nullptr);
    gemm_fp8<256, 3><<<dim3(8, 256), 256, DSM>>>(
        (const uint8_t*)p_m, (const uint8_t*)p_Wu,
        (const float*)p_bu, x, nullptr, out);
}

// round 8
// speedup vs baseline: 1.3156x; 1.0130x over previous
#include <cuda_runtime.h>
#include <cuda_bf16.h>
#include <cstdint>

#define BROWS 32768
#define CDIM  1024
#define CHDIM 256

// ---------------- scratch (device globals; no allocations allowed) ----------------
__device__ uint8_t g_t8[(size_t)BROWS * CDIM];    // LN output, fp8 e4m3
__device__ uint8_t g_h8[(size_t)BROWS * CHDIM];   // GLU output, fp8
__device__ uint8_t g_g8[(size_t)BROWS * CHDIM];   // gelu(FFN1), fp8
__device__ uint8_t g_m8[(size_t)BROWS * CHDIM];   // FFN2∘attn output, fp8
__device__ uint8_t g_Wdg8[512 * CDIM];            // interleaved [2j]=WdT_j,[2j+1]=WgT_j (K-major fp8)
__device__ float   g_bdg[512];                    // interleaved bd/bg
__device__ uint8_t g_W1T8[CHDIM * CHDIM];         // [n][k] fp8 (dw folded)
__device__ uint8_t g_W2T8[CHDIM * CHDIM];         // (W2·Wv·Wo)^T fp8
__device__ uint8_t g_WuT8[CDIM * CHDIM];          // (Wu + Wu·Wld·Wlu)^T fp8
__device__ float g_P[CHDIM * CHDIM];              // Wv@Wo
__device__ float g_T16[CHDIM * 16];               // Wu@Wld
__device__ float g_s16[16];                       // bu@Wld
__device__ float g_b1eff[CHDIM];
__device__ float g_b2eff[CHDIM];
__device__ float g_bueff[CDIM];

// ---------------- helpers ----------------
__device__ __forceinline__ void cp16cg(uint32_t s, const void* g) {
    asm volatile("cp.async.cg.shared.global [%0], [%1], 16;\n" :: "r"(s), "l"(g));
}
__device__ __forceinline__ void ldsm4(uint32_t* r, uint32_t addr) {
    asm volatile("ldmatrix.sync.aligned.m8n8.x4.shared.b16 {%0,%1,%2,%3}, [%4];"
                 : "=r"(r[0]), "=r"(r[1]), "=r"(r[2]), "=r"(r[3]) : "r"(addr));
}
__device__ __forceinline__ void mma_fp8(float* c, const uint32_t* a, uint32_t b0, uint32_t b1) {
    asm volatile("mma.sync.aligned.m16n8k32.row.col.f32.e4m3.e4m3.f32 "
                 "{%0,%1,%2,%3}, {%4,%5,%6,%7}, {%8,%9}, {%0,%1,%2,%3};\n"
                 : "+f"(c[0]), "+f"(c[1]), "+f"(c[2]), "+f"(c[3])
                 : "r"(a[0]), "r"(a[1]), "r"(a[2]), "r"(a[3]), "r"(b0), "r"(b1));
}
__device__ __forceinline__ uint16_t pk_e4m3_2(float lo, float hi) {
    uint16_t r;
    asm("cvt.rn.satfinite.e4m3x2.f32 %0, %1, %2;" : "=h"(r) : "f"(hi), "f"(lo));
    return r;
}
__device__ __forceinline__ uint32_t pk_e4m3_4(float a, float b, float c, float d) {
    return (uint32_t)pk_e4m3_2(a, b) | ((uint32_t)pk_e4m3_2(c, d) << 16);
}
__device__ __forceinline__ uint8_t pk_e4m3_1(float v) {
    return (uint8_t)pk_e4m3_2(v, 0.f);
}
__device__ __forceinline__ float sigm(float x) { return 1.f / (1.f + expf(-x)); }
__device__ __forceinline__ float gelu_t(float x) {
    return 0.5f * x * (1.f + tanhf(0.7978845608028654f * (x + 0.044715f * x * x * x)));
}

// ---------------- prep1: all weight transforms with no internal deps ----------------
// blocks: [0,256) P=Wv@Wo | [256,512) W1T8 | 512 b1eff | [513,1025) Wdg8 |
//         1025 bdg | [1026,1282) T16 | 1282 s16
__global__ void __launch_bounds__(256) prep1(
    const float* __restrict__ Wv, const float* __restrict__ Wo,
    const float* __restrict__ W1, const float* __restrict__ dww,
    const float* __restrict__ b1, const float* __restrict__ dwb,
    const float* __restrict__ Wd, const float* __restrict__ Wg,
    const float* __restrict__ bd, const float* __restrict__ bg,
    const float* __restrict__ Wu, const float* __restrict__ Wld,
    const float* __restrict__ bu) {
    __shared__ float buf[256];
    const int b = blockIdx.x, t = threadIdx.x;
    if (b < 256) {
        buf[t] = Wv[b * 256 + t];
        __syncthreads();
        float s = 0.f;
        #pragma unroll 8
        for (int k = 0; k < 256; k++) s += buf[k] * Wo[k * 256 + t];
        g_P[b * 256 + t] = s;
    } else if (b < 512) {
        const int i = b - 256;
        g_W1T8[t * 256 + i] = pk_e4m3_1(dww[i] * W1[i * 256 + t]);
    } else if (b == 512) {
        float s = b1[t];
        for (int i = 0; i < 256; i++) s += dwb[i] * W1[i * 256 + t];
        g_b1eff[t] = s;
    } else if (b < 1025) {
        const int f = b - 513;
        const int j = f >> 1;
        const float* W = (f & 1) ? Wg : Wd;
        const int k0 = t * 4;
        ((uint32_t*)g_Wdg8)[f * 256 + t] = pk_e4m3_4(
            W[(k0 + 0) * 256 + j], W[(k0 + 1) * 256 + j],
            W[(k0 + 2) * 256 + j], W[(k0 + 3) * 256 + j]);
    } else if (b == 1025) {
        for (int idx = t; idx < 512; idx += 256)
            g_bdg[idx] = (idx & 1) ? bg[idx >> 1] : bd[idx >> 1];
    } else if (b < 1282) {
        const int i = b - 1026;
        const int r = t & 15, kc = t >> 4;
        float s = 0.f;
        for (int k = kc * 64; k < kc * 64 + 64; k++)
            s += Wu[(size_t)i * 1024 + k] * Wld[k * 16 + r];
        buf[t] = s;
        __syncthreads();
        if (t < 16) {
            float acc = 0.f;
            #pragma unroll
            for (int c = 0; c < 16; c++) acc += buf[c * 16 + t];
            g_T16[i * 16 + t] = acc;
        }
    } else {
        if (t < 16) {
            float s = 0.f;
            for (int k = 0; k < 1024; k++) s += bu[k] * Wld[k * 16 + t];
            g_s16[t] = s;
        }
    }
}
// ---------------- prep2: transforms depending on P / T16 / s16 ----------------
// blocks: [0,256) W2T8 | 256 b2eff | [257,385) WuT8 (8 cols each) + bueff
__global__ void __launch_bounds__(256) prep2(
    const float* __restrict__ W2, const float* __restrict__ b2,
    const float* __restrict__ bv, const float* __restrict__ Wo,
    const float* __restrict__ bo,
    const float* __restrict__ Wu, const float* __restrict__ Wlu,
    const float* __restrict__ bu) {
    __shared__ float buf[256];
    const int b = blockIdx.x, t = threadIdx.x;
    if (b < 256) {
        buf[t] = W2[b * 256 + t];
        __syncthreads();
        float s = 0.f;
        #pragma unroll 8
        for (int k = 0; k < 256; k++) s += buf[k] * g_P[k * 256 + t];
        g_W2T8[t * 256 + b] = pk_e4m3_1(s);
    } else if (b == 256) {
        float s = bo[t];
        for (int k = 0; k < 256; k++) s += b2[k] * g_P[k * 256 + t] + bv[k] * Wo[k * 256 + t];
        g_b2eff[t] = s;
    } else {
        // 8 output columns n0..n0+7; thread t = Wu row; coalesced 32B/thread reads
        const int n0 = (b - 257) * 8;
        __shared__ float wl8[16][8];
        __shared__ float sb[8][256];
        if (t < 128) wl8[t >> 3][t & 7] = Wlu[(t >> 3) * 1024 + n0 + (t & 7)];
        __syncthreads();
        float s[8];
        const float4 w0 = *(const float4*)&Wu[(size_t)t * 1024 + n0];
        const float4 w1 = *(const float4*)&Wu[(size_t)t * 1024 + n0 + 4];
        s[0] = w0.x; s[1] = w0.y; s[2] = w0.z; s[3] = w0.w;
        s[4] = w1.x; s[5] = w1.y; s[6] = w1.z; s[7] = w1.w;
        #pragma unroll
        for (int r = 0; r < 16; r++) {
            const float tr = g_T16[t * 16 + r];
            #pragma unroll
            for (int c = 0; c < 8; c++) s[c] += tr * wl8[r][c];
        }
        #pragma unroll
        for (int c = 0; c < 8; c++) sb[c][t] = s[c];
        if (t < 8) {
            float bb = bu[n0 + t];
            #pragma unroll
            for (int r = 0; r < 16; r++) bb += g_s16[r] * wl8[r][t];
            g_bueff[n0 + t] = bb;
        }
        __syncthreads();
        // pack: 4 rows concurrently (t>>6 = row group), coalesced uint32 stores
        #pragma unroll
        for (int c = t >> 6; c < 8; c += 4) {
            const int tt = t & 63;
            ((uint32_t*)g_WuT8)[(size_t)(n0 + c) * 64 + tt] = pk_e4m3_4(
                sb[c][4 * tt], sb[c][4 * tt + 1], sb[c][4 * tt + 2], sb[c][4 * tt + 3]);
        }
    }
}

// ---------------- LayerNorm: x[row,1024] -> fp8 g_t8 ----------------
__global__ void __launch_bounds__(256) ln_kernel(const float* __restrict__ x,
                                                 const float* __restrict__ gamma,
                                                 const float* __restrict__ beta) {
    const int row = blockIdx.x;
    const int tid = threadIdx.x;
    const float4 v = ((const float4*)(x + (size_t)row * CDIM))[tid];
    float s  = v.x + v.y + v.z + v.w;
    float s2 = v.x * v.x + v.y * v.y + v.z * v.z + v.w * v.w;
    #pragma unroll
    for (int o = 16; o > 0; o >>= 1) {
        s  += __shfl_xor_sync(0xffffffffu, s, o);
        s2 += __shfl_xor_sync(0xffffffffu, s2, o);
    }
    __shared__ float rs[8], rq[8];
    const int w = tid >> 5, lane = tid & 31;
    if (lane == 0) { rs[w] = s; rq[w] = s2; }
    __syncthreads();
    float mu = 0.f, e2 = 0.f;
    #pragma unroll
    for (int i = 0; i < 8; i++) { mu += rs[i]; e2 += rq[i]; }
    mu *= (1.f / 1024.f);
    const float var = e2 * (1.f / 1024.f) - mu * mu;
    const float rstd = rsqrtf(var + 1e-5f);
    const float4 gm = ((const float4*)gamma)[tid];
    const float4 bt = ((const float4*)beta)[tid];
    ((uint32_t*)(g_t8 + (size_t)row * CDIM))[tid] = pk_e4m3_4(
        (v.x - mu) * rstd * gm.x + bt.x, (v.y - mu) * rstd * gm.y + bt.y,
        (v.z - mu) * rstd * gm.z + bt.z, (v.w - mu) * rstd * gm.w + bt.w);
}

// ---------------- FP8 QMMA GEMM: 128x128 CTA tile, KT=128B, 3-stage cp.async ----------
// Swizzle algebra: base addresses have bits[5:7)=0, SW128 mask depends on bits[7:10)
// only => swizzle(base + kk*32) == swizzle(base) ^ (kk*32), and +s*16384 commutes.
// So all smem addresses = precomputed base + stage-offset ^ kk-immediate.
// MODE 0: GLU over interleaved (d,g) adjacent cols -> fp8 [.,256]
// MODE 1: gelu(acc+bias) -> fp8   MODE 2: acc+bias -> fp8
// MODE 3: 0.5*(acc+bias) + 0.5*x -> fp32 [.,1024]
template<int KDIM, int MODE>
__global__ void __launch_bounds__(256, 2) gemm_fp8(
    const uint8_t* __restrict__ A,
    const uint8_t* __restrict__ BT,
    const float* __restrict__ bias,
    const float* __restrict__ xres,
    uint8_t* __restrict__ out8,
    float* __restrict__ outf) {
    constexpr int NKT = KDIM / 128;
    extern __shared__ __align__(1024) char dsm[];
    const uint32_t Ab = (uint32_t)__cvta_generic_to_shared(dsm);  // [3][128][128B]
    const uint32_t Bb = Ab + 49152;                               // [3][128][128B]
    const int tid = threadIdx.x, lane = tid & 31, w = tid >> 5;
    const int wm = w >> 2, wn = w & 3;
    const int mbase = blockIdx.y * 128, nbase = blockIdx.x * 128;

    float acc[4][4][4];
    #pragma unroll
    for (int mi = 0; mi < 4; mi++)
        #pragma unroll
        for (int nj = 0; nj < 4; nj++)
            #pragma unroll
            for (int q = 0; q < 4; q++) acc[mi][nj][q] = 0.f;

    // ---- precomputed fill addresses (smem offsets swizzled once; gmem row ptrs) ----
    uint32_t f_off[4];
    const uint8_t* gAp[4];
    const uint8_t* gBp[4];
    #pragma unroll
    for (int i = 0; i < 4; i++) {
        const int cid = tid + i * 256;
        const int rr = cid >> 3, cc = (cid & 7) * 16;
        uint32_t o = (uint32_t)(rr * 128 + cc);
        o ^= (o >> 3) & 0x70;
        f_off[i] = o;
        gAp[i] = A + (size_t)(mbase + rr) * KDIM + cc;
        gBp[i] = BT + (size_t)(nbase + rr) * KDIM + cc;
    }
    auto fill = [&](int s, int c) {
        const int k0 = c * 128;
        const uint32_t as = Ab + s * 16384, bs = Bb + s * 16384;
        #pragma unroll
        for (int i = 0; i < 4; i++) cp16cg(as + f_off[i], gAp[i] + k0);
        #pragma unroll
        for (int i = 0; i < 4; i++) cp16cg(bs + f_off[i], gBp[i] + k0);
        asm volatile("cp.async.commit_group;\n" ::: "memory");
    };

    // ---- precomputed ldmatrix base addresses (stage 0, kk 0) ----
    const int a_r  = wm * 64 + ((lane >> 3) & 1) * 8 + (lane & 7);
    const int a_cb = ((lane >> 4) & 1) * 16;
    const int b_r  = wn * 32 + ((lane >> 4) & 1) * 8 + (lane & 7);
    const int b_cb = ((lane >> 3) & 1) * 16;
    uint32_t a_sm[4], b_sm[2];
    #pragma unroll
    for (int mi = 0; mi < 4; mi++) {
        uint32_t o = (uint32_t)((a_r + mi * 16) * 128 + a_cb);
        o ^= (o >> 3) & 0x70;
        a_sm[mi] = Ab + o;
    }
    #pragma unroll
    for (int p = 0; p < 2; p++) {
        uint32_t o = (uint32_t)((b_r + p * 16) * 128 + b_cb);
        o ^= (o >> 3) & 0x70;
        b_sm[p] = Bb + o;
    }

    fill(0, 0);
    if (NKT > 1) fill(1, 1);
    int fi = 2;
    for (int i = 0; i < NKT; i++) {
        const int s = i % 3;
        if (i < NKT - 1) asm volatile("cp.async.wait_group 1;\n" ::: "memory");
        else             asm volatile("cp.async.wait_group 0;\n" ::: "memory");
        __syncthreads();
        if (fi < NKT) { fill(fi % 3, fi); fi++; }
        const uint32_t so = (uint32_t)(s * 16384);
        #pragma unroll
        for (int kk = 0; kk < 4; kk++) {
            uint32_t a[4][4], b[2][4];
            #pragma unroll
            for (int mi = 0; mi < 4; mi++)
                ldsm4(a[mi], (a_sm[mi] + so) ^ (uint32_t)(kk * 32));
            #pragma unroll
            for (int p = 0; p < 2; p++)
                ldsm4(b[p], (b_sm[p] + so) ^ (uint32_t)(kk * 32));
            #pragma unroll
            for (int mi = 0; mi < 4; mi++)
                #pragma unroll
                for (int nj = 0; nj < 4; nj++)
                    mma_fp8(acc[mi][nj], a[mi], b[nj >> 1][(nj & 1) * 2],
                            b[nj >> 1][(nj & 1) * 2 + 1]);
        }
    }

    #pragma unroll
    for (int mi = 0; mi < 4; mi++) {
        const int r0 = mbase + wm * 64 + mi * 16 + (lane >> 2);
        const int r1 = r0 + 8;
        #pragma unroll
        for (int nj = 0; nj < 4; nj++) {
            const int col = nbase + wn * 32 + nj * 8 + (lane & 3) * 2;
            const float* c = acc[mi][nj];
            if constexpr (MODE == 0) {
                const float b0 = bias[col], b1 = bias[col + 1];
                const int j = col >> 1;
                out8[(size_t)r0 * 256 + j] = pk_e4m3_1((c[0] + b0) * sigm(c[1] + b1));
                out8[(size_t)r1 * 256 + j] = pk_e4m3_1((c[2] + b0) * sigm(c[3] + b1));
            } else if constexpr (MODE == 1 || MODE == 2) {
                const float b0 = bias[col], b1 = bias[col + 1];
                float v00 = c[0] + b0, v01 = c[1] + b1, v10 = c[2] + b0, v11 = c[3] + b1;
                if constexpr (MODE == 1) {
                    v00 = gelu_t(v00); v01 = gelu_t(v01); v10 = gelu_t(v10); v11 = gelu_t(v11);
                }
                *(uint16_t*)&out8[(size_t)r0 * 256 + col] = pk_e4m3_2(v00, v01);
                *(uint16_t*)&out8[(size_t)r1 * 256 + col] = pk_e4m3_2(v10, v11);
            } else {
                const float b0 = bias[col], b1 = bias[col + 1];
                const float2 x0 = *(const float2*)&xres[(size_t)r0 * 1024 + col];
                const float2 x1 = *(const float2*)&xres[(size_t)r1 * 1024 + col];
                float2 o0 = make_float2(0.5f * (c[0] + b0) + 0.5f * x0.x,
                                        0.5f * (c[1] + b1) + 0.5f * x0.y);
                float2 o1 = make_float2(0.5f * (c[2] + b0) + 0.5f * x1.x,
                                        0.5f * (c[3] + b1) + 0.5f * x1.y);
                *(float2*)&outf[(size_t)r0 * 1024 + col] = o0;
                *(float2*)&outf[(size_t)r1 * 1024 + col] = o1;
            }
        }
    }
}

// ---------------- launch ----------------
extern "C" void kernel_launch(void* const* d_in, const int* in_sizes, int n_in,
                              void* d_out, int out_size) {
    (void)in_sizes; (void)n_in; (void)out_size;
    const float* x    = (const float*)d_in[0];
    const float* ln_g = (const float*)d_in[1];
    const float* ln_b = (const float*)d_in[2];
    const float* Wd   = (const float*)d_in[3];
    const float* bd   = (const float*)d_in[4];
    const float* Wg   = (const float*)d_in[5];
    const float* bg   = (const float*)d_in[6];
    const float* dww  = (const float*)d_in[7];
    const float* dwb  = (const float*)d_in[8];
    const float* W1   = (const float*)d_in[9];
    const float* b1   = (const float*)d_in[10];
    const float* W2   = (const float*)d_in[11];
    const float* b2   = (const float*)d_in[12];
    // d_in[13..16] = Wq, bq, Wk, bk : dead (softmax over a single key == 1)
    const float* Wv   = (const float*)d_in[17];
    const float* bv   = (const float*)d_in[18];
    const float* Wo   = (const float*)d_in[19];
    const float* bo   = (const float*)d_in[20];
    const float* Wu   = (const float*)d_in[21];
    const float* bu   = (const float*)d_in[22];
    const float* Wld  = (const float*)d_in[23];
    const float* Wlu  = (const float*)d_in[24];
    float* out = (float*)d_out;

    void *p_t, *p_h, *p_g, *p_m, *p_Wdg, *p_bdg, *p_W1, *p_W2, *p_Wu, *p_b1, *p_b2, *p_bu;
    cudaGetSymbolAddress(&p_t,   g_t8);
    cudaGetSymbolAddress(&p_h,   g_h8);
    cudaGetSymbolAddress(&p_g,   g_g8);
    cudaGetSymbolAddress(&p_m,   g_m8);
    cudaGetSymbolAddress(&p_Wdg, g_Wdg8);
    cudaGetSymbolAddress(&p_bdg, g_bdg);
    cudaGetSymbolAddress(&p_W1,  g_W1T8);
    cudaGetSymbolAddress(&p_W2,  g_W2T8);
    cudaGetSymbolAddress(&p_Wu,  g_WuT8);
    cudaGetSymbolAddress(&p_b1,  g_b1eff);
    cudaGetSymbolAddress(&p_b2,  g_b2eff);
    cudaGetSymbolAddress(&p_bu,  g_bueff);

    constexpr int DSM = 98304;  // 3 stages x (16KB A + 16KB B)
    static bool attr_done = false;
    if (!attr_done) {
        cudaFuncSetAttribute(gemm_fp8<1024, 0>, cudaFuncAttributeMaxDynamicSharedMemorySize, DSM);
        cudaFuncSetAttribute(gemm_fp8<256, 1>,  cudaFuncAttributeMaxDynamicSharedMemorySize, DSM);
        cudaFuncSetAttribute(gemm_fp8<256, 2>,  cudaFuncAttributeMaxDynamicSharedMemorySize, DSM);
        cudaFuncSetAttribute(gemm_fp8<256, 3>,  cudaFuncAttributeMaxDynamicSharedMemorySize, DSM);
        attr_done = true;
    }

    // launch order: prep1(0), prep2(1), ln(2), GEMM1(3) <- ncu -s5 lands here,
    // gemm2(4), gemm3(5), gemm4(6)
    prep1<<<1283, 256>>>(Wv, Wo, W1, dww, b1, dwb, Wd, Wg, bd, bg, Wu, Wld, bu);
    prep2<<<385, 256>>>(W2, b2, bv, Wo, bo, Wu, Wlu, bu);
    ln_kernel<<<BROWS, 256>>>(x, ln_g, ln_b);

    gemm_fp8<1024, 0><<<dim3(4, 256), 256, DSM>>>(
        (const uint8_t*)p_t, (const uint8_t*)p_Wdg,
        (const float*)p_bdg, nullptr, (uint8_t*)p_h, nullptr);
    gemm_fp8<256, 1><<<dim3(2, 256), 256, DSM>>>(
        (const uint8_t*)p_h, (const uint8_t*)p_W1,
        (const float*)p_b1, nullptr, (uint8_t*)p_g, nullptr);
    gemm_fp8<256, 2><<<dim3(2, 256), 256, DSM>>>(
        (const uint8_t*)p_g, (const uint8_t*)p_W2,
        (const float*)p_b2, nullptr, (uint8_t*)p_m, nullptr);
    gemm_fp8<256, 3><<<dim3(8, 256), 256, DSM>>>(
        (const uint8_t*)p_m, (const uint8_t*)p_Wu,
        (const float*)p_bu, x, nullptr, out);
}